// round 2
// baseline (speedup 1.0000x reference)
#include <cuda_runtime.h>
#include <math.h>

// Problem constants (fixed by reference setup_inputs)
#define B  4
#define T  4096
#define C  64
#define HS 64
#define BT (B * T)

#define ROWS   64      // attention rows per block
#define HROWS  72      // padded halo rows in smem (68 used: [-2, +65])
#define XSTR   65      // xs row stride (floats)
#define WSTR   68      // ws row stride (mult of 4 for 8B/16B loads)
#define OSTR   68      // q/k/v smem row stride (mult of 4)

#define NTHREADS        512
#define COMPUTE_THREADS 160    // warps 0-4
#define GEMM_THREADS    144    // 18 row-groups x 8 h-groups
#define ZERO_WARPS      11     // warps 5-15

// smem layout (floats)
#define WS_OFF 0
#define WS_SZ  (64 * WSTR)          // 4352
#define XS_OFF (WS_OFF + WS_SZ)
#define XS_SZ  (HROWS * XSTR)       // 4680
#define OS_SZ  (HROWS * OSTR)       // 4896
#define QS_OFF (XS_OFF + XS_SZ)
#define KS_OFF (QS_OFF + OS_SZ)
#define VS_OFF (KS_OFF + OS_SZ)
#define SMEM_FLOATS (VS_OFF + OS_SZ)             // 23720 floats
#define SMEM_BYTES  (SMEM_FLOATS * 4)            // 94880 bytes

typedef unsigned long long u64;

__device__ __forceinline__ u64 pack2(float a) {
    u64 r;
    asm("mov.b64 %0, {%1, %1};" : "=l"(r) : "f"(a));
    return r;
}
__device__ __forceinline__ void ffma2(u64& acc, u64 a, u64 b) {
    asm("fma.rn.f32x2 %0, %1, %2, %0;" : "+l"(acc) : "l"(a), "l"(b));
}

__global__ __launch_bounds__(NTHREADS, 2)
void fused_attn_kernel(const float* __restrict__ x,
                       const float* __restrict__ Wq,
                       const float* __restrict__ Wk,
                       const float* __restrict__ Wv,
                       float* __restrict__ op_out,    // [B*T, 64]
                       float* __restrict__ attn_out)  // [B, T, T]
{
    extern __shared__ float sm[];
    float* ws = sm + WS_OFF;
    float* xs = sm + XS_OFF;
    float* qs = sm + QS_OFF;
    float* ks = sm + KS_OFF;
    float* vs = sm + VS_OFF;

    const int tid  = threadIdx.x;
    const int wid  = tid >> 5;
    const int lane = tid & 31;
    const int blk  = blockIdx.x;       // 0..255
    const int b    = blk >> 6;         // 64 blocks per batch
    const int r0   = (blk & 63) << 6;  // first row (within batch) of this block

    // ========================= ZERO-FILL WARPS (5..15) ======================
    // Stream zeros into all 64 attn rows of this block, skipping the <=2
    // band float4 slots per row (written later by the compute warps).
    if (wid >= 5) {
        const int zw = wid - 5;
        const float4 z = make_float4(0.f, 0.f, 0.f, 0.f);
        for (int lt = zw; lt < ROWS; lt += ZERO_WARPS) {
            const int t  = r0 + lt;
            const int lo = max(t - 2, 0);
            const int hi = min(t + 2, T - 1);
            const int fa = lo >> 2;
            const int fb = hi >> 2;
            float4* row4 = reinterpret_cast<float4*>(
                attn_out + (size_t)b * T * T + (size_t)t * T);
            #pragma unroll 4
            for (int i4 = lane; i4 < T / 4; i4 += 32) {
                if (i4 != fa && i4 != fb) __stcs(&row4[i4], z);
            }
        }
        return;
    }

    // ========================= COMPUTE WARPS (0..4) =========================
    // ---- load x halo rows [r0-2, r0+69] (clamped to batch) into smem ----
    for (int idx = tid; idx < HROWS * 64; idx += COMPUTE_THREADS) {
        const int r = idx >> 6, c = idx & 63;
        const int tb = min(max(r0 + r - 2, 0), T - 1);
        xs[r * XSTR + c] = x[((size_t)(b * T + tb)) * C + c];
    }

    // ---- 3 GEMMs: q/k/v[r][h] = sum_c x[r][c] * W[h][c], rows 0..71 ----
    const float* Wm[3] = {Wq, Wk, Wv};
    float* Om[3] = {qs, ks, vs};

    #pragma unroll 1
    for (int m = 0; m < 3; ++m) {
        // load W transposed: ws[c][h]
        for (int idx = tid; idx < 64 * 64; idx += COMPUTE_THREADS) {
            const int h = idx >> 6, c = idx & 63;
            ws[c * WSTR + h] = Wm[m][idx];
        }
        asm volatile("bar.sync 1, %0;" :: "n"(COMPUTE_THREADS) : "memory");

        if (tid < GEMM_THREADS) {
            const int rr = (tid >> 3) << 2;    // 0,4,...,68
            const int h0 = (tid & 7) << 3;     // 0,8,...,56
            u64 acc[4][4];
            #pragma unroll
            for (int i = 0; i < 4; i++)
                #pragma unroll
                for (int j = 0; j < 4; j++) acc[i][j] = 0ULL;

            #pragma unroll 4
            for (int c = 0; c < 64; ++c) {
                const u64* wp = reinterpret_cast<const u64*>(&ws[c * WSTR + h0]);
                const u64 b0 = wp[0], b1 = wp[1], b2 = wp[2], b3 = wp[3];
                const u64 a0 = pack2(xs[(rr + 0) * XSTR + c]);
                const u64 a1 = pack2(xs[(rr + 1) * XSTR + c]);
                const u64 a2 = pack2(xs[(rr + 2) * XSTR + c]);
                const u64 a3 = pack2(xs[(rr + 3) * XSTR + c]);
                ffma2(acc[0][0], a0, b0); ffma2(acc[0][1], a0, b1);
                ffma2(acc[0][2], a0, b2); ffma2(acc[0][3], a0, b3);
                ffma2(acc[1][0], a1, b0); ffma2(acc[1][1], a1, b1);
                ffma2(acc[1][2], a1, b2); ffma2(acc[1][3], a1, b3);
                ffma2(acc[2][0], a2, b0); ffma2(acc[2][1], a2, b1);
                ffma2(acc[2][2], a2, b2); ffma2(acc[2][3], a2, b3);
                ffma2(acc[3][0], a3, b0); ffma2(acc[3][1], a3, b1);
                ffma2(acc[3][2], a3, b2); ffma2(acc[3][3], a3, b3);
            }
            float* orow = Om[m];
            #pragma unroll
            for (int i = 0; i < 4; i++)
                #pragma unroll
                for (int j = 0; j < 4; j++)
                    *reinterpret_cast<u64*>(
                        &orow[(rr + i) * OSTR + h0 + 2 * j]) = acc[i][j];
        }
        asm volatile("bar.sync 1, %0;" :: "n"(COMPUTE_THREADS) : "memory");
    }

    // ---- attention: 5-tap softmax per row; op row + band float4s ----
    for (int lt = wid; lt < ROWS; lt += 5) {
        const int t = r0 + lt;
        const float2 q2 =
            *reinterpret_cast<const float2*>(&qs[(lt + 2) * OSTR + 2 * lane]);

        float score[5];
        #pragma unroll
        for (int d = 0; d < 5; ++d) {
            const int tb = t - 2 + d;
            const bool valid = (unsigned)tb < (unsigned)T;
            float p = 0.f;
            if (valid) {
                const float2 k2 = *reinterpret_cast<const float2*>(
                    &ks[(lt + d) * OSTR + 2 * lane]);
                p = q2.x * k2.x + q2.y * k2.y;
            }
            #pragma unroll
            for (int off = 16; off > 0; off >>= 1)
                p += __shfl_xor_sync(0xFFFFFFFFu, p, off);
            // scale = C^-0.5 = 1/8; triu quirk: +1.0 for s > t (d > 2)
            score[d] = valid ? (p * 0.125f + (d > 2 ? 1.0f : 0.0f)) : -1e30f;
        }

        float mmax = score[0];
        #pragma unroll
        for (int d = 1; d < 5; ++d) mmax = fmaxf(mmax, score[d]);
        float p5[5], sum = 0.f;
        #pragma unroll
        for (int d = 0; d < 5; ++d) { p5[d] = __expf(score[d] - mmax); sum += p5[d]; }
        const float inv = 1.0f / sum;
        #pragma unroll
        for (int d = 0; d < 5; ++d) p5[d] *= inv;

        // op row: each lane owns 2 channels
        float2 acc = make_float2(0.f, 0.f);
        #pragma unroll
        for (int d = 0; d < 5; ++d) {
            const int tb = t - 2 + d;
            if ((unsigned)tb < (unsigned)T) {
                const float2 v2 = *reinterpret_cast<const float2*>(
                    &vs[(lt + d) * OSTR + 2 * lane]);
                acc.x += p5[d] * v2.x;
                acc.y += p5[d] * v2.y;
            }
        }
        *reinterpret_cast<float2*>(
            &op_out[((size_t)(b * T + t)) * HS + 2 * lane]) = acc;

        // band float4 slots (zero warps skipped these)
        const int lo = max(t - 2, 0);
        const int hi = min(t + 2, T - 1);
        const int fa = lo >> 2;
        const int fb = hi >> 2;
        #define BV(s_) (((s_) >= lo && (s_) <= hi)                         \
                          ? ((s_) == t - 2 ? p5[0]                         \
                           : (s_) == t - 1 ? p5[1]                         \
                           : (s_) == t     ? p5[2]                         \
                           : (s_) == t + 1 ? p5[3] : p5[4])                \
                          : 0.0f)
        const float4 va = make_float4(BV(4 * fa + 0), BV(4 * fa + 1),
                                      BV(4 * fa + 2), BV(4 * fa + 3));
        const float4 vb = make_float4(BV(4 * fb + 0), BV(4 * fb + 1),
                                      BV(4 * fb + 2), BV(4 * fb + 3));
        #undef BV

        float4* row4 = reinterpret_cast<float4*>(
            attn_out + (size_t)b * T * T + (size_t)t * T);
        if (lane == 0) __stcs(&row4[fa], va);
        if (lane == 1) __stcs(&row4[fb], vb);
    }
}

// ---------------------------------------------------------------------------
extern "C" void kernel_launch(void* const* d_in, const int* in_sizes, int n_in,
                              void* d_out, int out_size)
{
    const float* x  = (const float*)d_in[0];
    const float* Wq = (const float*)d_in[1];
    const float* Wk = (const float*)d_in[2];
    const float* Wv = (const float*)d_in[3];

    float* out = (float*)d_out;
    float* op_out   = out;                     // [B*T*HS]
    float* attn_out = out + (size_t)BT * HS;   // [B*T*T]

    cudaFuncSetAttribute(fused_attn_kernel,
                         cudaFuncAttributeMaxDynamicSharedMemorySize,
                         SMEM_BYTES);

    fused_attn_kernel<<<BT / ROWS, NTHREADS, SMEM_BYTES>>>(
        x, Wq, Wk, Wv, op_out, attn_out);
}

// round 3
// speedup vs baseline: 1.3621x; 1.3621x over previous
#include <cuda_runtime.h>
#include <math.h>

// Problem constants (fixed by reference setup_inputs)
#define B  4
#define T  4096
#define C  64
#define HS 64
#define BT (B * T)

// Scratch for q, k, v projections (device globals; no allocations allowed)
__device__ float g_q[BT * HS];
__device__ float g_k[BT * HS];
__device__ float g_v[BT * HS];

// Fork-join plumbing, created once at library init (host objects only).
static cudaStream_t g_s2;
static cudaEvent_t  g_evFork, g_evJoin;
namespace {
struct InitStreams {
    InitStreams() {
        cudaStreamCreateWithFlags(&g_s2, cudaStreamNonBlocking);
        cudaEventCreateWithFlags(&g_evFork, cudaEventDisableTiming);
        cudaEventCreateWithFlags(&g_evJoin, cudaEventDisableTiming);
    }
};
InitStreams g_initStreams;
}

// ---------------------------------------------------------------------------
// Kernel Z: zero-fill the attn matrix, skipping the <=2 band float4 slots per
// row (those are written by band_kernel, concurrently, at disjoint addresses).
// One warp per (b, t) row. Grid 2048 x 256 (proven 59.5% DRAM in R1).
// ---------------------------------------------------------------------------
__global__ __launch_bounds__(256, 8)
void zero_kernel(float* __restrict__ attn_out)   // [B, T, T]
{
    const int warp_in_blk = threadIdx.x >> 5;
    const int lane = threadIdx.x & 31;
    const int w = blockIdx.x * 8 + warp_in_blk;   // row id in [0, BT)
    const int b = w >> 12;
    const int t = w & (T - 1);

    const int lo = max(t - 2, 0);
    const int hi = min(t + 2, T - 1);
    const int fa = lo >> 2;
    const int fb = hi >> 2;

    float4* row4 = reinterpret_cast<float4*>(
        attn_out + (size_t)b * T * T + (size_t)t * T);
    const float4 z = make_float4(0.f, 0.f, 0.f, 0.f);

    #pragma unroll 4
    for (int i4 = lane; i4 < T / 4; i4 += 32) {
        if (i4 != fa && i4 != fb) __stcs(&row4[i4], z);
    }
}

// ---------------------------------------------------------------------------
// Kernel 1: QKV projection.  out[t][h] = sum_c x[t][c] * W[h][c]
// Grid: (BT/64, 3). Block: 256 threads. Tile: 64x64, 4x4 per thread.
// ---------------------------------------------------------------------------
__global__ __launch_bounds__(256, 4)
void qkv_kernel(const float* __restrict__ x,
                const float* __restrict__ Wq,
                const float* __restrict__ Wk,
                const float* __restrict__ Wv)
{
    __shared__ float xs[64 * 67];
    __shared__ float ws[64 * 65];

    const float* W;
    float* out;
    if (blockIdx.y == 0)      { W = Wq; out = g_q; }
    else if (blockIdx.y == 1) { W = Wk; out = g_k; }
    else                      { W = Wv; out = g_v; }

    const int row0 = blockIdx.x * 64;
    const int tid = threadIdx.x;

    #pragma unroll
    for (int idx = tid; idx < 64 * 64; idx += 256) {
        int h = idx >> 6, c = idx & 63;
        ws[c * 65 + h] = W[idx];
    }
    #pragma unroll
    for (int idx = tid; idx < 64 * 64; idx += 256) {
        int m = idx >> 6, c = idx & 63;
        xs[c * 67 + m] = x[(size_t)(row0 + m) * C + c];
    }
    __syncthreads();

    const int tm = (tid >> 4) * 4;
    const int tn = (tid & 15) * 4;

    float acc[4][4];
    #pragma unroll
    for (int i = 0; i < 4; i++)
        #pragma unroll
        for (int j = 0; j < 4; j++) acc[i][j] = 0.0f;

    #pragma unroll 8
    for (int c = 0; c < 64; ++c) {
        float a0 = xs[c * 67 + tm + 0];
        float a1 = xs[c * 67 + tm + 1];
        float a2 = xs[c * 67 + tm + 2];
        float a3 = xs[c * 67 + tm + 3];
        float b0 = ws[c * 65 + tn + 0];
        float b1 = ws[c * 65 + tn + 1];
        float b2 = ws[c * 65 + tn + 2];
        float b3 = ws[c * 65 + tn + 3];
        acc[0][0] += a0 * b0; acc[0][1] += a0 * b1; acc[0][2] += a0 * b2; acc[0][3] += a0 * b3;
        acc[1][0] += a1 * b0; acc[1][1] += a1 * b1; acc[1][2] += a1 * b2; acc[1][3] += a1 * b3;
        acc[2][0] += a2 * b0; acc[2][1] += a2 * b1; acc[2][2] += a2 * b2; acc[2][3] += a2 * b3;
        acc[3][0] += a3 * b0; acc[3][1] += a3 * b1; acc[3][2] += a3 * b2; acc[3][3] += a3 * b3;
    }

    #pragma unroll
    for (int i = 0; i < 4; i++) {
        float4 v4 = make_float4(acc[i][0], acc[i][1], acc[i][2], acc[i][3]);
        *reinterpret_cast<float4*>(&out[(size_t)(row0 + tm + i) * HS + tn]) = v4;
    }
}

// ---------------------------------------------------------------------------
// Kernel 2: band attention. One warp per (b, t) row: 5 dots, softmax, op row,
// and ONLY the <=2 band float4 slots of the attn row (zeros done elsewhere).
// ---------------------------------------------------------------------------
__global__ __launch_bounds__(256, 8)
void band_kernel(float* __restrict__ op_out,    // [B*T, 64]
                 float* __restrict__ attn_out)  // [B, T, T]
{
    const int warp_in_blk = threadIdx.x >> 5;
    const int lane = threadIdx.x & 31;
    const int w = blockIdx.x * 8 + warp_in_blk;
    const int b = w >> 12;
    const int t = w & (T - 1);

    const float2 myq = reinterpret_cast<const float2*>(g_q + (size_t)w * HS)[lane];

    float score[5];
    #pragma unroll
    for (int d = 0; d < 5; ++d) {
        const int s = t - 2 + d;
        const bool valid = (unsigned)s < (unsigned)T;
        float p = 0.0f;
        if (valid) {
            const float2 kk =
                reinterpret_cast<const float2*>(g_k + ((size_t)(b * T + s)) * HS)[lane];
            p = myq.x * kk.x + myq.y * kk.y;
        }
        #pragma unroll
        for (int off = 16; off > 0; off >>= 1)
            p += __shfl_xor_sync(0xFFFFFFFFu, p, off);
        // scale = C^-0.5 = 1/8 ; triu quirk: +1.0 when s > t (d > 2)
        score[d] = valid ? (p * 0.125f + (d > 2 ? 1.0f : 0.0f)) : -1e30f;
    }

    float m = score[0];
    #pragma unroll
    for (int d = 1; d < 5; ++d) m = fmaxf(m, score[d]);
    float p5[5], sum = 0.0f;
    #pragma unroll
    for (int d = 0; d < 5; ++d) { p5[d] = expf(score[d] - m); sum += p5[d]; }
    const float inv = 1.0f / sum;
    #pragma unroll
    for (int d = 0; d < 5; ++d) p5[d] *= inv;

    // op row
    float2 acc = make_float2(0.0f, 0.0f);
    #pragma unroll
    for (int d = 0; d < 5; ++d) {
        const int s = t - 2 + d;
        if ((unsigned)s < (unsigned)T) {
            const float2 vv =
                reinterpret_cast<const float2*>(g_v + ((size_t)(b * T + s)) * HS)[lane];
            acc.x += p5[d] * vv.x;
            acc.y += p5[d] * vv.y;
        }
    }
    reinterpret_cast<float2*>(op_out + (size_t)w * HS)[lane] = acc;

    // band float4 slots
    const int lo = max(t - 2, 0);
    const int hi = min(t + 2, T - 1);
    const int fa = lo >> 2;
    const int fb = hi >> 2;

    #define BV(s_) (((s_) >= lo && (s_) <= hi)                                   \
                      ? ((s_) == t - 2 ? p5[0]                                   \
                       : (s_) == t - 1 ? p5[1]                                   \
                       : (s_) == t     ? p5[2]                                   \
                       : (s_) == t + 1 ? p5[3] : p5[4])                          \
                      : 0.0f)
    const float4 va = make_float4(BV(4 * fa + 0), BV(4 * fa + 1),
                                  BV(4 * fa + 2), BV(4 * fa + 3));
    const float4 vb = make_float4(BV(4 * fb + 0), BV(4 * fb + 1),
                                  BV(4 * fb + 2), BV(4 * fb + 3));
    #undef BV

    float4* row4 = reinterpret_cast<float4*>(
        attn_out + (size_t)b * T * T + (size_t)t * T);
    if (lane == 0) __stcs(&row4[fa], va);
    if (lane == 1 && fb != fa) __stcs(&row4[fb], vb);
}

// ---------------------------------------------------------------------------
extern "C" void kernel_launch(void* const* d_in, const int* in_sizes, int n_in,
                              void* d_out, int out_size)
{
    const float* x  = (const float*)d_in[0];
    const float* Wq = (const float*)d_in[1];
    const float* Wk = (const float*)d_in[2];
    const float* Wv = (const float*)d_in[3];

    float* out = (float*)d_out;
    float* op_out   = out;                     // [B*T*HS]
    float* attn_out = out + (size_t)BT * HS;   // [B*T*T]

    // Fork: zero-fill runs on g_s2 concurrently with the qkv->band chain.
    cudaEventRecord(g_evFork, 0);
    cudaStreamWaitEvent(g_s2, g_evFork, 0);

    zero_kernel<<<BT / 8, 256, 0, g_s2>>>(attn_out);

    dim3 g1(BT / 64, 3);
    qkv_kernel<<<g1, 256>>>(x, Wq, Wk, Wv);
    band_kernel<<<BT / 8, 256>>>(op_out, attn_out);

    // Join: main stream waits for the zero-fill.
    cudaEventRecord(g_evJoin, g_s2);
    cudaStreamWaitEvent(0, g_evJoin, 0);
}